// round 3
// baseline (speedup 1.0000x reference)
#include <cuda_runtime.h>

// I2GNN fixed structure: G=64, N_PER_G=64, S=8, DEG=4, EMB=128, LAYERS=5.
// N=4096 nodes, 64 tuples/root. Fully fused per-root CTA; Xv lives in smem.
// R3: packed fp32x2 FMA GEMM + W k-tiles double-buffered in smem.

#define NN   4096
#define NPG  64
#define EMB  128
#define S    8
#define NLAY 5
#define NT   64
#define KT   16          // k-tile rows of W per stage

__device__ float g_lin[NN * EMB];
__device__ float g_node_s[NN];

typedef unsigned long long u64;

#define FMA2(d, a, b, c) \
    asm("fma.rn.f32x2 %0, %1, %2, %3;" : "=l"(d) : "l"(a), "l"(b), "l"(c))
#define PACK2S(d, f) do { unsigned _u = __float_as_uint(f); \
    asm("mov.b64 %0, {%1, %1};" : "=l"(d) : "r"(_u)); } while (0)
#define UNPACK2(lo, hi, d) do { unsigned _l, _h; \
    asm("mov.b64 {%0, %1}, %2;" : "=r"(_l), "=r"(_h) : "l"(d)); \
    lo = __uint_as_float(_l); hi = __uint_as_float(_h); } while (0)
#define LD2(p) (*(const u64*)(p))

// ---------------------------------------------------------------------------
__global__ void lin_kernel(const int* __restrict__ x,
                           const float* __restrict__ emb_x,
                           const float* __restrict__ w_ti,
                           const float* __restrict__ b_ti) {
    __shared__ float sXe[EMB];
    const int i = blockIdx.x;
    const int c = threadIdx.x;
    sXe[c] = emb_x[x[i] * EMB + c];
    __syncthreads();
    float acc = b_ti[c];
#pragma unroll 8
    for (int k = 0; k < EMB; ++k)
        acc = fmaf(sXe[k], w_ti[k * EMB + c], acc);
    g_lin[i * EMB + c] = acc;
}

// ---------------------------------------------------------------------------
// smem layout (floats)
#define SM_XV   0                       // 64*128 = 8192
#define SM_AGG  (NT * EMB)              // 8192
#define SM_EA   (2 * NT * EMB)          // 32*128 = 4096
#define SM_XE   (SM_EA + 32 * EMB)      // 128
#define SM_LIN  (SM_XE + EMB)           // 8*128 = 1024
#define SM_W    (SM_LIN + S * EMB)      // 2*KT*128 = 4096
#define SM_FLOATS (SM_W + 2 * KT * EMB)
#define SMEM_BYTES (SM_FLOATS * 4)      // ~102.9 KB

__global__ __launch_bounds__(256, 2)
void conv_kernel(const int* __restrict__ x,
                 const int* __restrict__ edge_attr,
                 const int* __restrict__ tuplefeat,
                 const float* __restrict__ emb_x,
                 const float* __restrict__ emb_ea,
                 const float* __restrict__ emb_tf,
                 const float* __restrict__ w_conv,
                 const float* __restrict__ b_conv,
                 const float* __restrict__ w_pred) {
    extern __shared__ float sm[];
    float* sXv  = sm + SM_XV;
    float* sAgg = sm + SM_AGG;
    float* sEa  = sm + SM_EA;
    float* sXe  = sm + SM_XE;
    float* sLin = sm + SM_LIN;
    float* sW   = sm + SM_W;

    const int i    = blockIdx.x;
    const int tid  = threadIdx.x;
    const int base = (i >> 6) << 6;
    const int im   = i & 63;

    if (tid < EMB) sXe[tid] = emb_x[x[i] * EMB + tid];

    for (int idx = tid; idx < S * EMB; idx += 256) {
        const int j = idx >> 7, c = idx & 127;
        const int jn = ((im + j) & 63) + base;
        sLin[idx] = g_lin[jn * EMB + c];
    }
    for (int idx = tid; idx < 32 * EMB; idx += 256) {
        const int e = idx >> 7, c = idx & 127;
        const int ok = e >> 2, di = e & 3;
        const int kg = ((im + ok) & 63) + base;
        sEa[idx] = emb_ea[edge_attr[kg * 4 + di] * EMB + c];
    }
    __syncthreads();

    // Xv init
    for (int idx = tid; idx < NT * EMB; idx += 256) {
        const int t = idx >> 7, c = idx & 127;
        const int j = t >> 3;
        const int tg = i * NT + t;
        const int tfi = tuplefeat[tg * 2 + (c >> 6)];
        const float tfv = emb_tf[tfi * (EMB / 2) + (c & 63)];
        sXv[idx] = sXe[c] * sLin[(j << 7) + c] * tfv;
    }
    __syncthreads();

    const int r0 = (tid >> 4) << 2;     // 4 rows
    const int c0 = (tid & 15) << 3;     // 8 cols

    for (int layer = 0; layer < NLAY; ++layer) {
        const float* __restrict__ W = w_conv + layer * EMB * EMB;
        const float* __restrict__ B = b_conv + layer * EMB;

        // prefetch W tile 0
        {
            const float4* src = (const float4*)W;
            float4* dst = (float4*)sW;
            for (int idx = tid; idx < KT * EMB / 4; idx += 256)
                dst[idx] = src[idx];
        }

        // messages + local segment_sum (f32x2, 2 channels/iter)
        for (int idx = tid; idx < NT * EMB / 2; idx += 256) {
            const int t = idx >> 6;
            const int c2 = (idx & 63) << 1;
            const int j8 = t & ~7, k = t & 7;
            const float* ear = sEa + ((k << 2) << 7) + c2;
            u64 a = 0ull;
            if (k < 7) FMA2(a, LD2(&sXv[((j8 + k + 1) << 7) + c2]), LD2(ear + 0 * EMB), a);
            if (k < 6) FMA2(a, LD2(&sXv[((j8 + k + 2) << 7) + c2]), LD2(ear + 1 * EMB), a);
            if (k > 0) FMA2(a, LD2(&sXv[((j8 + k - 1) << 7) + c2]), LD2(ear + 2 * EMB), a);
            if (k > 1) FMA2(a, LD2(&sXv[((j8 + k - 2) << 7) + c2]), LD2(ear + 3 * EMB), a);
            *(u64*)&sAgg[(t << 7) + c2] = a;
        }
        __syncthreads();   // sAgg ready + W tile 0 ready

        // GEMM 64x128 @ 128x128, packed f32x2, double-buffered W tiles
        u64 acc[4][4];
#pragma unroll
        for (int r = 0; r < 4; ++r)
#pragma unroll
            for (int p = 0; p < 4; ++p) acc[r][p] = 0ull;

        for (int t = 0; t < EMB / KT; ++t) {
            const int cur = t & 1;
            if (t < EMB / KT - 1) {      // load next tile while computing
                const float4* src = (const float4*)(W + (t + 1) * KT * EMB);
                float4* dst = (float4*)(sW + (cur ^ 1) * KT * EMB);
                for (int idx = tid; idx < KT * EMB / 4; idx += 256)
                    dst[idx] = src[idx];
            }
            const float* Wt = sW + cur * KT * EMB;
            const int k0 = t * KT;
#pragma unroll
            for (int kk4 = 0; kk4 < KT; kk4 += 4) {
                float4 a4[4];
#pragma unroll
                for (int r = 0; r < 4; ++r)
                    a4[r] = *(const float4*)&sAgg[(r0 + r) * EMB + k0 + kk4];
#pragma unroll
                for (int u = 0; u < 4; ++u) {
                    const ulonglong2 w01 = *(const ulonglong2*)(Wt + (kk4 + u) * EMB + c0);
                    const ulonglong2 w23 = *(const ulonglong2*)(Wt + (kk4 + u) * EMB + c0 + 4);
#pragma unroll
                    for (int r = 0; r < 4; ++r) {
                        const float av = (u == 0) ? a4[r].x : (u == 1) ? a4[r].y
                                       : (u == 2) ? a4[r].z : a4[r].w;
                        u64 ap; PACK2S(ap, av);
                        FMA2(acc[r][0], ap, w01.x, acc[r][0]);
                        FMA2(acc[r][1], ap, w01.y, acc[r][1]);
                        FMA2(acc[r][2], ap, w23.x, acc[r][2]);
                        FMA2(acc[r][3], ap, w23.y, acc[r][3]);
                    }
                }
            }
            __syncthreads();             // tile consumed / next tile written
        }

        // bias + relu + residual
        float bb[8];
#pragma unroll
        for (int cc = 0; cc < 8; ++cc) bb[cc] = B[c0 + cc];
#pragma unroll
        for (int r = 0; r < 4; ++r)
#pragma unroll
            for (int p = 0; p < 4; ++p) {
                float lo, hi;
                UNPACK2(lo, hi, acc[r][p]);
                lo += bb[2 * p];     lo = lo > 0.f ? lo : 0.f;
                hi += bb[2 * p + 1]; hi = hi > 0.f ? hi : 0.f;
                sXv[(r0 + r) * EMB + c0 + 2 * p]     += lo;
                sXv[(r0 + r) * EMB + c0 + 2 * p + 1] += hi;
            }
        __syncthreads();
    }

    // max over k per pair
    for (int idx = tid; idx < S * EMB; idx += 256) {
        const int j = idx >> 7, c = idx & 127;
        const float* row = sXv + ((j << 3) << 7) + c;
        float m = row[0];
#pragma unroll
        for (int k = 1; k < S; ++k) m = fmaxf(m, row[k << 7]);
        sAgg[idx] = m;
    }
    __syncthreads();

    // node dot w_pred
    float part = 0.f;
    for (int c = tid; c < EMB; c += 256) {
        float nv = 0.f;
#pragma unroll
        for (int j = 0; j < S; ++j) nv += sAgg[(j << 7) + c];
        part += nv * w_pred[c];
    }
#pragma unroll
    for (int o = 16; o; o >>= 1) part += __shfl_down_sync(0xffffffffu, part, o);
    if ((tid & 31) == 0) sXe[tid >> 5] = part;
    __syncthreads();
    if (tid == 0) {
        float s = 0.f;
#pragma unroll
        for (int w = 0; w < 8; ++w) s += sXe[w];
        g_node_s[i] = s;
    }
}

// ---------------------------------------------------------------------------
__global__ void final_kernel(const float* __restrict__ b_pred,
                             float* __restrict__ out) {
    const int g = threadIdx.x;
    float s = b_pred[0];
#pragma unroll 8
    for (int n = 0; n < NPG; ++n) s += g_node_s[g * NPG + n];
    out[g] = s;
}

// ---------------------------------------------------------------------------
extern "C" void kernel_launch(void* const* d_in, const int* in_sizes, int n_in,
                              void* d_out, int out_size) {
    const int* x         = (const int*)d_in[0];
    const int* edge_attr = (const int*)d_in[1];
    const int* tuplefeat = (const int*)d_in[2];
    int w0 = (n_in >= 21 && in_sizes[11] == 1) ? 12 : 11;
    const float* emb_x  = (const float*)d_in[w0 + 0];
    const float* emb_ea = (const float*)d_in[w0 + 1];
    const float* emb_tf = (const float*)d_in[w0 + 2];
    const float* w_ti   = (const float*)d_in[w0 + 3];
    const float* b_ti   = (const float*)d_in[w0 + 4];
    const float* w_conv = (const float*)d_in[w0 + 5];
    const float* b_conv = (const float*)d_in[w0 + 6];
    const float* w_pred = (const float*)d_in[w0 + 7];
    const float* b_pred = (const float*)d_in[w0 + 8];
    float* out = (float*)d_out;

    cudaFuncSetAttribute(conv_kernel,
                         cudaFuncAttributeMaxDynamicSharedMemorySize, SMEM_BYTES);

    lin_kernel<<<NN, EMB>>>(x, emb_x, w_ti, b_ti);
    conv_kernel<<<NN, 256, SMEM_BYTES>>>(x, edge_attr, tuplefeat,
                                         emb_x, emb_ea, emb_tf,
                                         w_conv, b_conv, w_pred);
    final_kernel<<<1, NPG>>>(b_pred, out);
}

// round 5
// speedup vs baseline: 2.0354x; 2.0354x over previous
#include <cuda_runtime.h>

// I2GNN fixed structure: G=64, N_PER_G=64, S=8, DEG=4, EMB=128, LAYERS=5.
// R4: GEMM on tensor cores via mma.sync.m16n8k8.tf32 (fp32 accumulate).
// Residual path stays exact fp32; only the conv branch is tf32-quantized.

#define NN   4096
#define NPG  64
#define EMB  128
#define S    8
#define NLAY 5
#define NT   64
#define KT   16          // W k-tile rows per stage
#define XST  132         // sXv row stride (floats) - bank-conflict-free frags
#define AST  132         // sAggT row stride
#define WST  20          // sWt row stride (per 16-k tile)

__device__ float g_lin[NN * EMB];
__device__ float g_node_s[NN];

typedef unsigned long long u64;
typedef unsigned int u32;

#define FMA2(d, a, b, c) \
    asm("fma.rn.f32x2 %0, %1, %2, %3;" : "=l"(d) : "l"(a), "l"(b), "l"(c))
#define UNPACK2(lo, hi, d) do { unsigned _l, _h; \
    asm("mov.b64 {%0, %1}, %2;" : "=r"(_l), "=r"(_h) : "l"(d)); \
    lo = __uint_as_float(_l); hi = __uint_as_float(_h); } while (0)
#define LD2(p) (*(const u64*)(p))
#define CVT_TF32(u, f) asm("cvt.rna.tf32.f32 %0, %1;" : "=r"(u) : "f"(f))

#define MMA_TF32(c, a, b0, b1) \
    asm("mma.sync.aligned.m16n8k8.row.col.f32.tf32.tf32.f32 " \
        "{%0,%1,%2,%3}, {%4,%5,%6,%7}, {%8,%9}, {%0,%1,%2,%3};" \
        : "+f"((c)[0]), "+f"((c)[1]), "+f"((c)[2]), "+f"((c)[3]) \
        : "r"((a)[0]), "r"((a)[1]), "r"((a)[2]), "r"((a)[3]), \
          "r"(b0), "r"(b1))

// ---------------------------------------------------------------------------
__global__ void lin_kernel(const int* __restrict__ x,
                           const float* __restrict__ emb_x,
                           const float* __restrict__ w_ti,
                           const float* __restrict__ b_ti) {
    __shared__ float sXe[EMB];
    const int i = blockIdx.x;
    const int c = threadIdx.x;
    sXe[c] = emb_x[x[i] * EMB + c];
    __syncthreads();
    float acc = b_ti[c];
#pragma unroll 8
    for (int k = 0; k < EMB; ++k)
        acc = fmaf(sXe[k], w_ti[k * EMB + c], acc);
    g_lin[i * EMB + c] = acc;
}

// ---------------------------------------------------------------------------
// smem layout (float units)
#define SM_XV   0                        // 64*132 = 8448
#define SM_AGG  8448                     // 64*132 = 8448 (tf32 bits)
#define SM_EA   16896                    // 32*128 = 4096
#define SM_LIN  20992                    // 8*128  = 1024
#define SM_XE   22016                    // 128
#define SM_W    22144                    // 2*128*20 = 5120 (tf32 bits)
#define SM_FLOATS 27264
#define SMEM_BYTES (SM_FLOATS * 4)       // ~106.5 KB -> 2 CTAs/SM

__global__ __launch_bounds__(256, 2)
void conv_kernel(const int* __restrict__ x,
                 const int* __restrict__ edge_attr,
                 const int* __restrict__ tuplefeat,
                 const float* __restrict__ emb_x,
                 const float* __restrict__ emb_ea,
                 const float* __restrict__ emb_tf,
                 const float* __restrict__ w_conv,
                 const float* __restrict__ b_conv,
                 const float* __restrict__ w_pred) {
    extern __shared__ float sm[];
    float* sXv   = sm + SM_XV;
    u32*   sAggT = (u32*)(sm + SM_AGG);
    float* sEa   = sm + SM_EA;
    float* sLin  = sm + SM_LIN;
    float* sXe   = sm + SM_XE;
    u32*   sW    = (u32*)(sm + SM_W);

    const int i    = blockIdx.x;
    const int tid  = threadIdx.x;
    const int base = (i >> 6) << 6;
    const int im   = i & 63;

    const int wid  = tid >> 5;
    const int lane = tid & 31;
    const int l4   = lane >> 2;      // 0..7
    const int lq   = lane & 3;       // 0..3
    const int mrow0 = (wid & 1) * 32;
    const int ncol0 = (wid >> 1) * 32;

    if (tid < EMB) sXe[tid] = emb_x[x[i] * EMB + tid];

    for (int idx = tid; idx < S * EMB; idx += 256) {
        const int j = idx >> 7, c = idx & 127;
        const int jn = ((im + j) & 63) + base;
        sLin[idx] = g_lin[jn * EMB + c];
    }
    for (int idx = tid; idx < 32 * EMB; idx += 256) {
        const int e = idx >> 7, c = idx & 127;
        const int ok = e >> 2, di = e & 3;
        const int kg = ((im + ok) & 63) + base;
        sEa[idx] = emb_ea[edge_attr[kg * 4 + di] * EMB + c];
    }
    __syncthreads();

    // Xv init (exact fp32)
    for (int idx = tid; idx < NT * EMB; idx += 256) {
        const int t = idx >> 7, c = idx & 127;
        const int j = t >> 3;
        const int tg = i * NT + t;
        const int tfi = tuplefeat[tg * 2 + (c >> 6)];
        const float tfv = emb_tf[tfi * (EMB / 2) + (c & 63)];
        sXv[t * XST + c] = sXe[c] * sLin[(j << 7) + c] * tfv;
    }
    __syncthreads();

    for (int layer = 0; layer < NLAY; ++layer) {
        const float* __restrict__ W = w_conv + layer * EMB * EMB;
        const float* __restrict__ B = b_conv + layer * EMB;

        // --- messages + local segment_sum -> tf32 into sAggT ---
        for (int idx = tid; idx < NT * EMB / 2; idx += 256) {
            const int t = idx >> 6;
            const int c2 = (idx & 63) << 1;
            const int j8 = t & ~7, k = t & 7;
            const float* ear = sEa + ((k << 2) << 7) + c2;
            u64 a = 0ull;
            if (k < 7) FMA2(a, LD2(&sXv[(j8 + k + 1) * XST + c2]), LD2(ear + 0 * EMB), a);
            if (k < 6) FMA2(a, LD2(&sXv[(j8 + k + 2) * XST + c2]), LD2(ear + 1 * EMB), a);
            if (k > 0) FMA2(a, LD2(&sXv[(j8 + k - 1) * XST + c2]), LD2(ear + 2 * EMB), a);
            if (k > 1) FMA2(a, LD2(&sXv[(j8 + k - 2) * XST + c2]), LD2(ear + 3 * EMB), a);
            float lo, hi; UNPACK2(lo, hi, a);
            u32 ulo, uhi; CVT_TF32(ulo, lo); CVT_TF32(uhi, hi);
            sAggT[t * AST + c2]     = ulo;
            sAggT[t * AST + c2 + 1] = uhi;
        }
        // --- prefetch W tile 0 (transposed to [n][k], tf32) ---
        for (int idx = tid; idx < KT * EMB; idx += 256) {
            const int kt = idx >> 7, n = idx & 127;
            u32 u; CVT_TF32(u, W[kt * EMB + n]);
            sW[n * WST + kt] = u;
        }
        __syncthreads();

        // --- GEMM 64x128 @ 128x128 on tensor cores ---
        float acc[2][4][4];
#pragma unroll
        for (int mt = 0; mt < 2; ++mt)
#pragma unroll
            for (int nt = 0; nt < 4; ++nt)
#pragma unroll
                for (int r = 0; r < 4; ++r) acc[mt][nt][r] = 0.f;

        for (int t = 0; t < EMB / KT; ++t) {
            const u32* bufc = sW + (t & 1) * (EMB * WST);
            if (t < EMB / KT - 1) {
                u32* bufn = sW + ((t + 1) & 1) * (EMB * WST);
                const float* Wt = W + (t + 1) * KT * EMB;
                for (int idx = tid; idx < KT * EMB; idx += 256) {
                    const int kt = idx >> 7, n = idx & 127;
                    u32 u; CVT_TF32(u, Wt[kt * EMB + n]);
                    bufn[n * WST + kt] = u;
                }
            }
            const int k0 = t * KT;
#pragma unroll
            for (int ks = 0; ks < 2; ++ks) {
                const int kk = ks * 8;
                u32 afr[2][4];
#pragma unroll
                for (int mt = 0; mt < 2; ++mt) {
                    const int row = mrow0 + mt * 16 + l4;
                    afr[mt][0] = sAggT[row * AST + k0 + kk + lq];
                    afr[mt][1] = sAggT[(row + 8) * AST + k0 + kk + lq];
                    afr[mt][2] = sAggT[row * AST + k0 + kk + 4 + lq];
                    afr[mt][3] = sAggT[(row + 8) * AST + k0 + kk + 4 + lq];
                }
#pragma unroll
                for (int nt = 0; nt < 4; ++nt) {
                    const int col = ncol0 + nt * 8 + l4;
                    const u32 b0 = bufc[col * WST + kk + lq];
                    const u32 b1 = bufc[col * WST + kk + 4 + lq];
                    MMA_TF32(acc[0][nt], afr[0], b0, b1);
                    MMA_TF32(acc[1][nt], afr[1], b0, b1);
                }
            }
            __syncthreads();
        }

        // --- epilogue: bias + relu + residual (exact fp32 carry) ---
#pragma unroll
        for (int mt = 0; mt < 2; ++mt) {
            const int row = mrow0 + mt * 16 + l4;
#pragma unroll
            for (int nt = 0; nt < 4; ++nt) {
                const int col = ncol0 + nt * 8 + 2 * lq;
                const float b0v = B[col], b1v = B[col + 1];
                float v;
                v = acc[mt][nt][0] + b0v; v = v > 0.f ? v : 0.f;
                sXv[row * XST + col] += v;
                v = acc[mt][nt][1] + b1v; v = v > 0.f ? v : 0.f;
                sXv[row * XST + col + 1] += v;
                v = acc[mt][nt][2] + b0v; v = v > 0.f ? v : 0.f;
                sXv[(row + 8) * XST + col] += v;
                v = acc[mt][nt][3] + b1v; v = v > 0.f ? v : 0.f;
                sXv[(row + 8) * XST + col + 1] += v;
            }
        }
        __syncthreads();
    }

    // --- pooling: max over k per pair -> sLin[j][c] ---
    for (int idx = tid; idx < S * EMB; idx += 256) {
        const int j = idx >> 7, c = idx & 127;
        const float* row = sXv + (j << 3) * XST + c;
        float m = row[0];
#pragma unroll
        for (int k = 1; k < S; ++k) m = fmaxf(m, row[k * XST]);
        sLin[idx] = m;
    }
    __syncthreads();

    // --- node dot w_pred ---
    float part = 0.f;
    for (int c = tid; c < EMB; c += 256) {
        float nv = 0.f;
#pragma unroll
        for (int j = 0; j < S; ++j) nv += sLin[(j << 7) + c];
        part += nv * w_pred[c];
    }
#pragma unroll
    for (int o = 16; o; o >>= 1) part += __shfl_down_sync(0xffffffffu, part, o);
    if ((tid & 31) == 0) sXe[tid >> 5] = part;
    __syncthreads();
    if (tid == 0) {
        float s = 0.f;
#pragma unroll
        for (int w = 0; w < 8; ++w) s += sXe[w];
        g_node_s[i] = s;
    }
}

// ---------------------------------------------------------------------------
__global__ void final_kernel(const float* __restrict__ b_pred,
                             float* __restrict__ out) {
    const int g = threadIdx.x;
    float s = b_pred[0];
#pragma unroll 8
    for (int n = 0; n < NPG; ++n) s += g_node_s[g * NPG + n];
    out[g] = s;
}

// ---------------------------------------------------------------------------
extern "C" void kernel_launch(void* const* d_in, const int* in_sizes, int n_in,
                              void* d_out, int out_size) {
    const int* x         = (const int*)d_in[0];
    const int* edge_attr = (const int*)d_in[1];
    const int* tuplefeat = (const int*)d_in[2];
    int w0 = (n_in >= 21 && in_sizes[11] == 1) ? 12 : 11;
    const float* emb_x  = (const float*)d_in[w0 + 0];
    const float* emb_ea = (const float*)d_in[w0 + 1];
    const float* emb_tf = (const float*)d_in[w0 + 2];
    const float* w_ti   = (const float*)d_in[w0 + 3];
    const float* b_ti   = (const float*)d_in[w0 + 4];
    const float* w_conv = (const float*)d_in[w0 + 5];
    const float* b_conv = (const float*)d_in[w0 + 6];
    const float* w_pred = (const float*)d_in[w0 + 7];
    const float* b_pred = (const float*)d_in[w0 + 8];
    float* out = (float*)d_out;

    cudaFuncSetAttribute(conv_kernel,
                         cudaFuncAttributeMaxDynamicSharedMemorySize, SMEM_BYTES);

    lin_kernel<<<NN, EMB>>>(x, emb_x, w_ti, b_ti);
    conv_kernel<<<NN, 256, SMEM_BYTES>>>(x, edge_attr, tuplefeat,
                                         emb_x, emb_ea, emb_tf,
                                         w_conv, b_conv, w_pred);
    final_kernel<<<1, NPG>>>(b_pred, out);
}

// round 6
// speedup vs baseline: 3.2713x; 1.6072x over previous
#include <cuda_runtime.h>

// I2GNN fixed structure: G=64, N_PER_G=64, S=8, DEG=4, EMB=128, LAYERS=5.
// R5: W pre-converted to tf32 mma B-fragment layout (once, global);
//     conv CTA: messages (warp=k, lane=4ch) -> tf32 -> m16n8k8 MMA with
//     B-frags streamed via LDG.128, only 2 barriers per layer.

#define NN   4096
#define NPG  64
#define EMB  128
#define S    8
#define NLAY 5
#define NT   64
#define XST  132         // sXv row stride (floats)
#define AST  132         // sAggT row stride (u32)

__device__ float g_lin[NN * EMB];
__device__ float g_node_s[NN];
// B fragments: [layer][ks(16)][cg(4)][lane(32)][8]
__device__ unsigned int g_wfrag[NLAY * 16 * 4 * 32 * 8];

typedef unsigned long long u64;
typedef unsigned int u32;

#define FMA2(d, a, b, c) \
    asm("fma.rn.f32x2 %0, %1, %2, %3;" : "=l"(d) : "l"(a), "l"(b), "l"(c))
#define UNPACK2(lo, hi, d) do { unsigned _l, _h; \
    asm("mov.b64 {%0, %1}, %2;" : "=r"(_l), "=r"(_h) : "l"(d)); \
    lo = __uint_as_float(_l); hi = __uint_as_float(_h); } while (0)
#define CVT_TF32(u, f) asm("cvt.rna.tf32.f32 %0, %1;" : "=r"(u) : "f"(f))

#define MMA_TF32(c, a, b0, b1) \
    asm("mma.sync.aligned.m16n8k8.row.col.f32.tf32.tf32.f32 " \
        "{%0,%1,%2,%3}, {%4,%5,%6,%7}, {%8,%9}, {%0,%1,%2,%3};" \
        : "+f"((c)[0]), "+f"((c)[1]), "+f"((c)[2]), "+f"((c)[3]) \
        : "r"((a)[0]), "r"((a)[1]), "r"((a)[2]), "r"((a)[3]), \
          "r"(b0), "r"(b1))

// ---------------------------------------------------------------------------
// W -> tf32 B-fragment layout.  element q of thread (layer, ks, cg, lane):
//   nt = q&3, half = q>>2
//   col  = cg*32 + nt*8 + (lane>>2)          (n index)
//   krow = ks*8 + half*4 + (lane&3)          (k index)
__global__ void wfrag_kernel(const float* __restrict__ w_conv) {
    const int idx = blockIdx.x * 256 + threadIdx.x;     // 81920 total
    const int q     = idx & 7;
    const int lane  = (idx >> 3) & 31;
    const int cg    = (idx >> 8) & 3;
    const int ks    = (idx >> 10) & 15;
    const int layer = idx >> 14;
    const int nt = q & 3, half = q >> 2;
    const int col  = cg * 32 + nt * 8 + (lane >> 2);
    const int krow = ks * 8 + half * 4 + (lane & 3);
    u32 u; CVT_TF32(u, w_conv[layer * EMB * EMB + krow * EMB + col]);
    g_wfrag[idx] = u;
}

// ---------------------------------------------------------------------------
__global__ void lin_kernel(const int* __restrict__ x,
                           const float* __restrict__ emb_x,
                           const float* __restrict__ w_ti,
                           const float* __restrict__ b_ti) {
    __shared__ float sXe[EMB];
    const int i = blockIdx.x;
    const int c = threadIdx.x;
    sXe[c] = emb_x[x[i] * EMB + c];
    __syncthreads();
    float acc = b_ti[c];
#pragma unroll 8
    for (int k = 0; k < EMB; ++k)
        acc = fmaf(sXe[k], w_ti[k * EMB + c], acc);
    g_lin[i * EMB + c] = acc;
}

// ---------------------------------------------------------------------------
// smem layout (float units)
#define SM_XV   0                        // 64*132 = 8448
#define SM_AGG  8448                     // 64*132 = 8448 (u32 tf32)
#define SM_EA   16896                    // 32*128 = 4096
#define SM_LIN  20992                    // 8*128  = 1024
#define SM_XE   22016                    // 128
#define SM_FLOATS 22144
#define SMEM_BYTES (SM_FLOATS * 4)       // ~86.5 KB -> 2 CTAs/SM

__global__ __launch_bounds__(256, 2)
void conv_kernel(const int* __restrict__ x,
                 const int* __restrict__ edge_attr,
                 const int* __restrict__ tuplefeat,
                 const float* __restrict__ emb_x,
                 const float* __restrict__ emb_ea,
                 const float* __restrict__ emb_tf,
                 const float* __restrict__ b_conv,
                 const float* __restrict__ w_pred) {
    extern __shared__ float sm[];
    float* sXv   = sm + SM_XV;
    u32*   sAggT = (u32*)(sm + SM_AGG);
    float* sEa   = sm + SM_EA;
    float* sLin  = sm + SM_LIN;
    float* sXe   = sm + SM_XE;

    const int i    = blockIdx.x;
    const int tid  = threadIdx.x;
    const int base = (i >> 6) << 6;
    const int im   = i & 63;

    const int wid  = tid >> 5;
    const int lane = tid & 31;
    const int l4   = lane >> 2;
    const int lq   = lane & 3;
    const int mrow0 = (wid & 1) * 32;
    const int ncol0 = (wid >> 1) * 32;
    const int cg    = wid >> 1;

    if (tid < EMB) sXe[tid] = emb_x[x[i] * EMB + tid];

    for (int idx = tid; idx < S * EMB; idx += 256) {
        const int j = idx >> 7, c = idx & 127;
        const int jn = ((im + j) & 63) + base;
        sLin[idx] = g_lin[jn * EMB + c];
    }
    for (int idx = tid; idx < 32 * EMB; idx += 256) {
        const int e = idx >> 7, c = idx & 127;
        const int ok = e >> 2, di = e & 3;
        const int kg = ((im + ok) & 63) + base;
        sEa[idx] = emb_ea[edge_attr[kg * 4 + di] * EMB + c];
    }
    __syncthreads();

    // Xv init (exact fp32)
    for (int idx = tid; idx < NT * EMB; idx += 256) {
        const int t = idx >> 7, c = idx & 127;
        const int j = t >> 3;
        const int tg = i * NT + t;
        const int tfi = tuplefeat[tg * 2 + (c >> 6)];
        const float tfv = emb_tf[tfi * (EMB / 2) + (c & 63)];
        sXv[t * XST + c] = sXe[c] * sLin[(j << 7) + c] * tfv;
    }
    __syncthreads();

    // message-stage constants: this warp owns k = wid, lane owns 4 channels
    const int mk = wid;
    const int c4 = lane << 2;
    const float* eaK = sEa + ((mk << 2) << 7) + c4;   // 4 rows, stride EMB

    for (int layer = 0; layer < NLAY; ++layer) {
        const float* __restrict__ B = b_conv + layer * EMB;

        // --- messages + local segment_sum -> tf32 into sAggT ---
        {
            const float4 e0 = *(const float4*)(eaK + 0 * EMB);
            const float4 e1 = *(const float4*)(eaK + 1 * EMB);
            const float4 e2 = *(const float4*)(eaK + 2 * EMB);
            const float4 e3 = *(const float4*)(eaK + 3 * EMB);
            const u64 e0a = ((const u64*)&e0)[0], e0b = ((const u64*)&e0)[1];
            const u64 e1a = ((const u64*)&e1)[0], e1b = ((const u64*)&e1)[1];
            const u64 e2a = ((const u64*)&e2)[0], e2b = ((const u64*)&e2)[1];
            const u64 e3a = ((const u64*)&e3)[0], e3b = ((const u64*)&e3)[1];
#pragma unroll
            for (int j = 0; j < S; ++j) {
                const int t = (j << 3) + mk;
                u64 a = 0ull, b = 0ull;
                if (mk < 7) {
                    const u64* p = (const u64*)&sXv[(t + 1) * XST + c4];
                    FMA2(a, p[0], e0a, a); FMA2(b, p[1], e0b, b);
                }
                if (mk < 6) {
                    const u64* p = (const u64*)&sXv[(t + 2) * XST + c4];
                    FMA2(a, p[0], e1a, a); FMA2(b, p[1], e1b, b);
                }
                if (mk > 0) {
                    const u64* p = (const u64*)&sXv[(t - 1) * XST + c4];
                    FMA2(a, p[0], e2a, a); FMA2(b, p[1], e2b, b);
                }
                if (mk > 1) {
                    const u64* p = (const u64*)&sXv[(t - 2) * XST + c4];
                    FMA2(a, p[0], e3a, a); FMA2(b, p[1], e3b, b);
                }
                float f0, f1, f2, f3;
                UNPACK2(f0, f1, a); UNPACK2(f2, f3, b);
                uint4 o;
                CVT_TF32(o.x, f0); CVT_TF32(o.y, f1);
                CVT_TF32(o.z, f2); CVT_TF32(o.w, f3);
                *(uint4*)&sAggT[t * AST + c4] = o;
            }
        }
        __syncthreads();

        // --- GEMM 64x128 @ 128x128, B-frags streamed from g_wfrag ---
        float acc[2][4][4];
#pragma unroll
        for (int mt = 0; mt < 2; ++mt)
#pragma unroll
            for (int nt = 0; nt < 4; ++nt)
#pragma unroll
                for (int r = 0; r < 4; ++r) acc[mt][nt][r] = 0.f;

        const u32* wf = g_wfrag + ((layer * 16 * 4) + cg) * 256 + lane * 8;
        uint4 bfa = *(const uint4*)(wf);
        uint4 bfb = *(const uint4*)(wf + 4);

#pragma unroll
        for (int ks = 0; ks < 16; ++ks) {
            uint4 nba, nbb;
            if (ks < 15) {
                const u32* nwf = wf + (ks + 1) * 1024;
                nba = *(const uint4*)(nwf);
                nbb = *(const uint4*)(nwf + 4);
            }
            const int kk = ks * 8;
            u32 afr[2][4];
#pragma unroll
            for (int mt = 0; mt < 2; ++mt) {
                const int row = mrow0 + mt * 16 + l4;
                afr[mt][0] = sAggT[row * AST + kk + lq];
                afr[mt][1] = sAggT[(row + 8) * AST + kk + lq];
                afr[mt][2] = sAggT[row * AST + kk + 4 + lq];
                afr[mt][3] = sAggT[(row + 8) * AST + kk + 4 + lq];
            }
            MMA_TF32(acc[0][0], afr[0], bfa.x, bfb.x);
            MMA_TF32(acc[1][0], afr[1], bfa.x, bfb.x);
            MMA_TF32(acc[0][1], afr[0], bfa.y, bfb.y);
            MMA_TF32(acc[1][1], afr[1], bfa.y, bfb.y);
            MMA_TF32(acc[0][2], afr[0], bfa.z, bfb.z);
            MMA_TF32(acc[1][2], afr[1], bfa.z, bfb.z);
            MMA_TF32(acc[0][3], afr[0], bfa.w, bfb.w);
            MMA_TF32(acc[1][3], afr[1], bfa.w, bfb.w);
            bfa = nba; bfb = nbb;
        }

        // --- epilogue: bias + relu + residual (exact fp32 carry) ---
#pragma unroll
        for (int mt = 0; mt < 2; ++mt) {
            const int row = mrow0 + mt * 16 + l4;
#pragma unroll
            for (int nt = 0; nt < 4; ++nt) {
                const int col = ncol0 + nt * 8 + 2 * lq;
                const float b0v = B[col], b1v = B[col + 1];
                float v;
                v = acc[mt][nt][0] + b0v; v = v > 0.f ? v : 0.f;
                sXv[row * XST + col] += v;
                v = acc[mt][nt][1] + b1v; v = v > 0.f ? v : 0.f;
                sXv[row * XST + col + 1] += v;
                v = acc[mt][nt][2] + b0v; v = v > 0.f ? v : 0.f;
                sXv[(row + 8) * XST + col] += v;
                v = acc[mt][nt][3] + b1v; v = v > 0.f ? v : 0.f;
                sXv[(row + 8) * XST + col + 1] += v;
            }
        }
        __syncthreads();
    }

    // --- pooling: max over k per pair ---
    for (int idx = tid; idx < S * EMB; idx += 256) {
        const int j = idx >> 7, c = idx & 127;
        const float* row = sXv + (j << 3) * XST + c;
        float m = row[0];
#pragma unroll
        for (int k = 1; k < S; ++k) m = fmaxf(m, row[k * XST]);
        sLin[idx] = m;
    }
    __syncthreads();

    // --- node dot w_pred ---
    float part = 0.f;
    for (int c = tid; c < EMB; c += 256) {
        float nv = 0.f;
#pragma unroll
        for (int j = 0; j < S; ++j) nv += sLin[(j << 7) + c];
        part += nv * w_pred[c];
    }
#pragma unroll
    for (int o = 16; o; o >>= 1) part += __shfl_down_sync(0xffffffffu, part, o);
    if ((tid & 31) == 0) sXe[tid >> 5] = part;
    __syncthreads();
    if (tid == 0) {
        float s = 0.f;
#pragma unroll
        for (int w = 0; w < 8; ++w) s += sXe[w];
        g_node_s[i] = s;
    }
}

// ---------------------------------------------------------------------------
__global__ void final_kernel(const float* __restrict__ b_pred,
                             float* __restrict__ out) {
    const int g = threadIdx.x;
    float s = b_pred[0];
#pragma unroll 8
    for (int n = 0; n < NPG; ++n) s += g_node_s[g * NPG + n];
    out[g] = s;
}

// ---------------------------------------------------------------------------
extern "C" void kernel_launch(void* const* d_in, const int* in_sizes, int n_in,
                              void* d_out, int out_size) {
    const int* x         = (const int*)d_in[0];
    const int* edge_attr = (const int*)d_in[1];
    const int* tuplefeat = (const int*)d_in[2];
    int w0 = (n_in >= 21 && in_sizes[11] == 1) ? 12 : 11;
    const float* emb_x  = (const float*)d_in[w0 + 0];
    const float* emb_ea = (const float*)d_in[w0 + 1];
    const float* emb_tf = (const float*)d_in[w0 + 2];
    const float* w_ti   = (const float*)d_in[w0 + 3];
    const float* b_ti   = (const float*)d_in[w0 + 4];
    const float* w_conv = (const float*)d_in[w0 + 5];
    const float* b_conv = (const float*)d_in[w0 + 6];
    const float* w_pred = (const float*)d_in[w0 + 7];
    const float* b_pred = (const float*)d_in[w0 + 8];
    float* out = (float*)d_out;

    cudaFuncSetAttribute(conv_kernel,
                         cudaFuncAttributeMaxDynamicSharedMemorySize, SMEM_BYTES);

    wfrag_kernel<<<NLAY * 16 * 4 * 32 * 8 / 256, 256>>>(w_conv);
    lin_kernel<<<NN, EMB>>>(x, emb_x, w_ti, b_ti);
    conv_kernel<<<NN, 256, SMEM_BYTES>>>(x, edge_attr, tuplefeat,
                                         emb_x, emb_ea, emb_tf,
                                         b_conv, w_pred);
    final_kernel<<<1, NPG>>>(b_pred, out);
}

// round 9
// speedup vs baseline: 4.9093x; 1.5007x over previous
#include <cuda_runtime.h>
#include <cuda_bf16.h>

// I2GNN fixed structure: G=64, N_PER_G=64, S=8, DEG=4, EMB=128, LAYERS=5.
// R8: bf16 m16n8k16 MMA (fp32 accum), ldmatrix A-frags, pre-packed B-frags,
//     occupancy 3. Residual carry stays exact fp32.

#define NN   4096
#define NPG  64
#define EMB  128
#define S    8
#define NLAY 5
#define NT   64
#define XST  132         // sXv row stride (floats)
#define ASTB 136         // sAggB row stride (bf16/u16 units)

__device__ float g_lin[NN * EMB];
__device__ float g_node_s[NN];
// bf16 B fragments: [layer][ks(8)][cg(4)][lane(32)][8]  (q = nt*2+reg)
__device__ unsigned int g_wfrag[NLAY * 8 * 4 * 32 * 8];

typedef unsigned long long u64;
typedef unsigned int u32;
typedef unsigned short u16;

#define FMA2(d, a, b, c) \
    asm("fma.rn.f32x2 %0, %1, %2, %3;" : "=l"(d) : "l"(a), "l"(b), "l"(c))
#define UNPACK2(lo, hi, d) do { unsigned _l, _h; \
    asm("mov.b64 {%0, %1}, %2;" : "=r"(_l), "=r"(_h) : "l"(d)); \
    lo = __uint_as_float(_l); hi = __uint_as_float(_h); } while (0)
// pack {hi,lo} floats -> bf16x2 (hi in upper 16 bits)
#define PACKBF(u, lo, hi) \
    asm("cvt.rn.bf16x2.f32 %0, %1, %2;" : "=r"(u) : "f"(hi), "f"(lo))

#define MMA_BF16(c, a, b0, b1) \
    asm("mma.sync.aligned.m16n8k16.row.col.f32.bf16.bf16.f32 " \
        "{%0,%1,%2,%3}, {%4,%5,%6,%7}, {%8,%9}, {%0,%1,%2,%3};" \
        : "+f"((c)[0]), "+f"((c)[1]), "+f"((c)[2]), "+f"((c)[3]) \
        : "r"((a)[0]), "r"((a)[1]), "r"((a)[2]), "r"((a)[3]), \
          "r"(b0), "r"(b1))

#define LDSM4(r, addr) \
    asm("ldmatrix.sync.aligned.m8n8.x4.shared.b16 {%0,%1,%2,%3}, [%4];" \
        : "=r"((r)[0]), "=r"((r)[1]), "=r"((r)[2]), "=r"((r)[3]) : "r"(addr))

// ---------------------------------------------------------------------------
// W -> bf16 B-fragment layout for m16n8k16.
// element (layer, ks, cg, lane, q): nt = q>>1, reg = q&1
//   col = cg*32 + nt*8 + (lane>>2)
//   k0  = ks*16 + reg*8 + (lane&3)*2   -> pack {W[k0][col], W[k0+1][col]}
__global__ void wfrag_kernel(const float* __restrict__ w_conv) {
    const int idx = blockIdx.x * 256 + threadIdx.x;     // 40960 total
    const int q     = idx & 7;
    const int lane  = (idx >> 3) & 31;
    const int cg    = (idx >> 8) & 3;
    const int ks    = (idx >> 10) & 7;
    const int layer = idx >> 13;
    const int nt = q >> 1, reg = q & 1;
    const int col = cg * 32 + nt * 8 + (lane >> 2);
    const int k0  = ks * 16 + reg * 8 + (lane & 3) * 2;
    const float lo = w_conv[layer * EMB * EMB + k0 * EMB + col];
    const float hi = w_conv[layer * EMB * EMB + (k0 + 1) * EMB + col];
    u32 u; PACKBF(u, lo, hi);
    g_wfrag[idx] = u;
}

// ---------------------------------------------------------------------------
__global__ void lin_kernel(const int* __restrict__ x,
                           const float* __restrict__ emb_x,
                           const float* __restrict__ w_ti,
                           const float* __restrict__ b_ti) {
    __shared__ float sXe[EMB];
    const int i = blockIdx.x;
    const int c = threadIdx.x;
    sXe[c] = emb_x[x[i] * EMB + c];
    __syncthreads();
    float a0 = 0.f, a1 = 0.f, a2 = 0.f, a3 = 0.f;
#pragma unroll 8
    for (int k = 0; k < EMB; k += 4) {
        a0 = fmaf(sXe[k + 0], w_ti[(k + 0) * EMB + c], a0);
        a1 = fmaf(sXe[k + 1], w_ti[(k + 1) * EMB + c], a1);
        a2 = fmaf(sXe[k + 2], w_ti[(k + 2) * EMB + c], a2);
        a3 = fmaf(sXe[k + 3], w_ti[(k + 3) * EMB + c], a3);
    }
    g_lin[i * EMB + c] = b_ti[c] + ((a0 + a1) + (a2 + a3));
}

// ---------------------------------------------------------------------------
// smem layout (float units)
#define SM_XV   0                        // 64*132 = 8448
#define SM_AGG  8448                     // u16 64*136 = 4352 floats
#define SM_EA   12800                    // 32*128 = 4096
#define SM_LIN  16896                    // 8*128 = 1024
#define SM_XE   17920                    // 128
#define SM_FLOATS 18048
#define SMEM_BYTES (SM_FLOATS * 4)       // 72192 B -> 3 CTAs/SM

__global__ __launch_bounds__(256, 3)
void conv_kernel(const int* __restrict__ x,
                 const int* __restrict__ edge_attr,
                 const int* __restrict__ tuplefeat,
                 const float* __restrict__ emb_x,
                 const float* __restrict__ emb_ea,
                 const float* __restrict__ emb_tf,
                 const float* __restrict__ b_conv,
                 const float* __restrict__ w_pred) {
    extern __shared__ float sm[];
    float* sXv   = sm + SM_XV;
    u16*   sAggB = (u16*)(sm + SM_AGG);
    float* sEa   = sm + SM_EA;
    float* sLin  = sm + SM_LIN;
    float* sXe   = sm + SM_XE;

    const int i    = blockIdx.x;
    const int tid  = threadIdx.x;
    const int base = (i >> 6) << 6;
    const int im   = i & 63;

    const int wid  = tid >> 5;
    const int lane = tid & 31;
    const int l4   = lane >> 2;
    const int lq   = lane & 3;
    const int mrow0 = (wid & 1) * 32;
    const int ncol0 = (wid >> 1) * 32;
    const int cg    = wid >> 1;

    // ldmatrix per-lane address parts
    const int rowsel = (lane & 7) + ((lane >> 3) & 1) * 8;
    const int colsel = (lane >> 4) * 8;
    const u32 aBase = (u32)__cvta_generic_to_shared(sAggB);
    const u32 aAddr0 = aBase + ((mrow0 + rowsel) * ASTB + colsel) * 2;
    const u32 aAddr1 = aAddr0 + 16 * ASTB * 2;

    if (tid < EMB) sXe[tid] = emb_x[x[i] * EMB + tid];

    for (int idx = tid; idx < S * EMB; idx += 256) {
        const int j = idx >> 7, c = idx & 127;
        const int jn = ((im + j) & 63) + base;
        sLin[idx] = g_lin[jn * EMB + c];
    }
    for (int idx = tid; idx < 32 * EMB; idx += 256) {
        const int e = idx >> 7, c = idx & 127;
        const int ok = e >> 2, di = e & 3;
        const int kg = ((im + ok) & 63) + base;
        sEa[idx] = emb_ea[edge_attr[kg * 4 + di] * EMB + c];
    }
    __syncthreads();

    // Xv init (exact fp32)
    for (int idx = tid; idx < NT * EMB; idx += 256) {
        const int t = idx >> 7, c = idx & 127;
        const int j = t >> 3;
        const int tg = i * NT + t;
        const int tfi = tuplefeat[tg * 2 + (c >> 6)];
        const float tfv = emb_tf[tfi * (EMB / 2) + (c & 63)];
        sXv[t * XST + c] = sXe[c] * sLin[(j << 7) + c] * tfv;
    }
    __syncthreads();

    // message-stage constants: warp owns k = wid, lane owns 4 channels
    const int mk = wid;
    const int c4 = lane << 2;
    const float* eaK = sEa + ((mk << 2) << 7) + c4;

    for (int layer = 0; layer < NLAY; ++layer) {
        const float* __restrict__ B = b_conv + layer * EMB;

        // --- messages + local segment_sum -> bf16 into sAggB ---
        {
            const float4 e0 = *(const float4*)(eaK + 0 * EMB);
            const float4 e1 = *(const float4*)(eaK + 1 * EMB);
            const float4 e2 = *(const float4*)(eaK + 2 * EMB);
            const float4 e3 = *(const float4*)(eaK + 3 * EMB);
            const u64 e0a = ((const u64*)&e0)[0], e0b = ((const u64*)&e0)[1];
            const u64 e1a = ((const u64*)&e1)[0], e1b = ((const u64*)&e1)[1];
            const u64 e2a = ((const u64*)&e2)[0], e2b = ((const u64*)&e2)[1];
            const u64 e3a = ((const u64*)&e3)[0], e3b = ((const u64*)&e3)[1];
#pragma unroll
            for (int j = 0; j < S; ++j) {
                const int t = (j << 3) + mk;
                u64 a = 0ull, b = 0ull;
                if (mk < 7) {
                    const u64* p = (const u64*)&sXv[(t + 1) * XST + c4];
                    FMA2(a, p[0], e0a, a); FMA2(b, p[1], e0b, b);
                }
                if (mk < 6) {
                    const u64* p = (const u64*)&sXv[(t + 2) * XST + c4];
                    FMA2(a, p[0], e1a, a); FMA2(b, p[1], e1b, b);
                }
                if (mk > 0) {
                    const u64* p = (const u64*)&sXv[(t - 1) * XST + c4];
                    FMA2(a, p[0], e2a, a); FMA2(b, p[1], e2b, b);
                }
                if (mk > 1) {
                    const u64* p = (const u64*)&sXv[(t - 2) * XST + c4];
                    FMA2(a, p[0], e3a, a); FMA2(b, p[1], e3b, b);
                }
                float f0, f1, f2, f3;
                UNPACK2(f0, f1, a); UNPACK2(f2, f3, b);
                u32 w0, w1;
                PACKBF(w0, f0, f1);
                PACKBF(w1, f2, f3);
                u64 pk = ((u64)w1 << 32) | w0;
                *(u64*)&sAggB[t * ASTB + c4] = pk;
            }
        }
        __syncthreads();

        // --- GEMM 64x128 @ 128x128, bf16 MMA ---
        float acc[2][4][4];
#pragma unroll
        for (int mt = 0; mt < 2; ++mt)
#pragma unroll
            for (int nt = 0; nt < 4; ++nt)
#pragma unroll
                for (int r = 0; r < 4; ++r) acc[mt][nt][r] = 0.f;

        const u32* wf = g_wfrag + ((layer * 8 * 4) + cg) * 256 + lane * 8;
        uint4 bfa = *(const uint4*)(wf);
        uint4 bfb = *(const uint4*)(wf + 4);

#pragma unroll
        for (int ks = 0; ks < 8; ++ks) {
            uint4 nba, nbb;
            if (ks < 7) {
                const u32* nwf = wf + (ks + 1) * 1024;
                nba = *(const uint4*)(nwf);
                nbb = *(const uint4*)(nwf + 4);
            }
            u32 afr0[4], afr1[4];
            LDSM4(afr0, aAddr0 + ks * 32);
            LDSM4(afr1, aAddr1 + ks * 32);
            MMA_BF16(acc[0][0], afr0, bfa.x, bfa.y);
            MMA_BF16(acc[1][0], afr1, bfa.x, bfa.y);
            MMA_BF16(acc[0][1], afr0, bfa.z, bfa.w);
            MMA_BF16(acc[1][1], afr1, bfa.z, bfa.w);
            MMA_BF16(acc[0][2], afr0, bfb.x, bfb.y);
            MMA_BF16(acc[1][2], afr1, bfb.x, bfb.y);
            MMA_BF16(acc[0][3], afr0, bfb.z, bfb.w);
            MMA_BF16(acc[1][3], afr1, bfb.z, bfb.w);
            bfa = nba; bfb = nbb;
        }

        // --- epilogue: bias + relu + residual (exact fp32 carry) ---
#pragma unroll
        for (int mt = 0; mt < 2; ++mt) {
            const int row = mrow0 + mt * 16 + l4;
#pragma unroll
            for (int nt = 0; nt < 4; ++nt) {
                const int col = ncol0 + nt * 8 + 2 * lq;
                const float b0v = B[col], b1v = B[col + 1];
                float v;
                v = acc[mt][nt][0] + b0v; v = v > 0.f ? v : 0.f;
                sXv[row * XST + col] += v;
                v = acc[mt][nt][1] + b1v; v = v > 0.f ? v : 0.f;
                sXv[row * XST + col + 1] += v;
                v = acc[mt][nt][2] + b0v; v = v > 0.f ? v : 0.f;
                sXv[(row + 8) * XST + col] += v;
                v = acc[mt][nt][3] + b1v; v = v > 0.f ? v : 0.f;
                sXv[(row + 8) * XST + col + 1] += v;
            }
        }
        __syncthreads();
    }

    // --- pooling: max over k per pair ---
    for (int idx = tid; idx < S * EMB; idx += 256) {
        const int j = idx >> 7, c = idx & 127;
        const float* row = sXv + (j << 3) * XST + c;
        float m = row[0];
#pragma unroll
        for (int k = 1; k < S; ++k) m = fmaxf(m, row[k * XST]);
        sLin[idx] = m;
    }
    __syncthreads();

    // --- node dot w_pred ---
    float part = 0.f;
    for (int c = tid; c < EMB; c += 256) {
        float nv = 0.f;
#pragma unroll
        for (int j = 0; j < S; ++j) nv += sLin[(j << 7) + c];
        part += nv * w_pred[c];
    }
#pragma unroll
    for (int o = 16; o; o >>= 1) part += __shfl_down_sync(0xffffffffu, part, o);
    if ((tid & 31) == 0) sXe[tid >> 5] = part;
    __syncthreads();
    if (tid == 0) {
        float s = 0.f;
#pragma unroll
        for (int w = 0; w < 8; ++w) s += sXe[w];
        g_node_s[i] = s;
    }
}

// ---------------------------------------------------------------------------
__global__ void final_kernel(const float* __restrict__ b_pred,
                             float* __restrict__ out) {
    __shared__ float sp[2];
    const int g = blockIdx.x;
    const int t = threadIdx.x;       // 64
    float v = g_node_s[g * NPG + t];
#pragma unroll
    for (int o = 16; o; o >>= 1) v += __shfl_down_sync(0xffffffffu, v, o);
    if ((t & 31) == 0) sp[t >> 5] = v;
    __syncthreads();
    if (t == 0) out[g] = sp[0] + sp[1] + b_pred[0];
}

// ---------------------------------------------------------------------------
extern "C" void kernel_launch(void* const* d_in, const int* in_sizes, int n_in,
                              void* d_out, int out_size) {
    const int* x         = (const int*)d_in[0];
    const int* edge_attr = (const int*)d_in[1];
    const int* tuplefeat = (const int*)d_in[2];
    int w0 = (n_in >= 21 && in_sizes[11] == 1) ? 12 : 11;
    const float* emb_x  = (const float*)d_in[w0 + 0];
    const float* emb_ea = (const float*)d_in[w0 + 1];
    const float* emb_tf = (const float*)d_in[w0 + 2];
    const float* w_ti   = (const float*)d_in[w0 + 3];
    const float* b_ti   = (const float*)d_in[w0 + 4];
    const float* w_conv = (const float*)d_in[w0 + 5];
    const float* b_conv = (const float*)d_in[w0 + 6];
    const float* w_pred = (const float*)d_in[w0 + 7];
    const float* b_pred = (const float*)d_in[w0 + 8];
    float* out = (float*)d_out;

    cudaFuncSetAttribute(conv_kernel,
                         cudaFuncAttributeMaxDynamicSharedMemorySize, SMEM_BYTES);

    wfrag_kernel<<<NLAY * 8 * 4 * 32 * 8 / 256, 256>>>(w_conv);
    lin_kernel<<<NN, EMB>>>(x, emb_x, w_ti, b_ti);
    conv_kernel<<<NN, 256, SMEM_BYTES>>>(x, edge_attr, tuplefeat,
                                         emb_x, emb_ea, emb_tf,
                                         b_conv, w_pred);
    final_kernel<<<NPG, NPG>>>(b_pred, out);
}

// round 13
// speedup vs baseline: 5.3188x; 1.0834x over previous
#include <cuda_runtime.h>
#include <cuda_bf16.h>

// I2GNN fixed structure: G=64, N_PER_G=64, S=8, DEG=4, EMB=128, LAYERS=5.
// R9: warp = all 64 M-rows x 16 N-cols; whole layer's B-frags prefetched to
//     registers (2 batches of 4 LDG.128, latency hidden under message stage);
//     float2 epilogue; tuplefeat staged in smem. bf16 MMA, fp32 residual.

#define NN   4096
#define NPG  64
#define EMB  128
#define S    8
#define NLAY 5
#define NT   64
#define XST  132         // sXv row stride (floats)
#define ASTB 136         // sAggB row stride (u16 units)

__device__ float g_lin[NN * EMB];
__device__ float g_node_s[NN];
// bf16 B frags: [layer][warp(8)][ks(8)][lane(32)][4]   (r: nt=r>>1, reg=r&1)
__device__ unsigned int g_wfrag[NLAY * 8 * 8 * 32 * 4];

typedef unsigned long long u64;
typedef unsigned int u32;
typedef unsigned short u16;

#define FMA2(d, a, b, c) \
    asm("fma.rn.f32x2 %0, %1, %2, %3;" : "=l"(d) : "l"(a), "l"(b), "l"(c))
#define UNPACK2(lo, hi, d) do { unsigned _l, _h; \
    asm("mov.b64 {%0, %1}, %2;" : "=r"(_l), "=r"(_h) : "l"(d)); \
    lo = __uint_as_float(_l); hi = __uint_as_float(_h); } while (0)
#define PACKBF(u, lo, hi) \
    asm("cvt.rn.bf16x2.f32 %0, %1, %2;" : "=r"(u) : "f"(hi), "f"(lo))

#define MMA_BF16(c, a, b0, b1) \
    asm("mma.sync.aligned.m16n8k16.row.col.f32.bf16.bf16.f32 " \
        "{%0,%1,%2,%3}, {%4,%5,%6,%7}, {%8,%9}, {%0,%1,%2,%3};" \
        : "+f"((c)[0]), "+f"((c)[1]), "+f"((c)[2]), "+f"((c)[3]) \
        : "r"((a)[0]), "r"((a)[1]), "r"((a)[2]), "r"((a)[3]), \
          "r"(b0), "r"(b1))

#define LDSM4(r, addr) \
    asm("ldmatrix.sync.aligned.m8n8.x4.shared.b16 {%0,%1,%2,%3}, [%4];" \
        : "=r"((r)[0]), "=r"((r)[1]), "=r"((r)[2]), "=r"((r)[3]) : "r"(addr))

// ---------------------------------------------------------------------------
// element (layer, w, ks, lane, r): nt=r>>1, reg=r&1
//   col = w*16 + nt*8 + (lane>>2)
//   k0  = ks*16 + reg*8 + (lane&3)*2 -> pack {W[k0][col], W[k0+1][col]}
__global__ void wfrag_kernel(const float* __restrict__ w_conv) {
    const int idx = blockIdx.x * 256 + threadIdx.x;     // 40960 total
    const int r     = idx & 3;
    const int lane  = (idx >> 2) & 31;
    const int ks    = (idx >> 7) & 7;
    const int w     = (idx >> 10) & 7;
    const int layer = idx >> 13;
    const int nt = r >> 1, reg = r & 1;
    const int col = w * 16 + nt * 8 + (lane >> 2);
    const int k0  = ks * 16 + reg * 8 + (lane & 3) * 2;
    const float lo = w_conv[layer * EMB * EMB + k0 * EMB + col];
    const float hi = w_conv[layer * EMB * EMB + (k0 + 1) * EMB + col];
    u32 u; PACKBF(u, lo, hi);
    g_wfrag[idx] = u;
}

// ---------------------------------------------------------------------------
__global__ void lin_kernel(const int* __restrict__ x,
                           const float* __restrict__ emb_x,
                           const float* __restrict__ w_ti,
                           const float* __restrict__ b_ti) {
    __shared__ float sXe[EMB];
    const int i = blockIdx.x;
    const int c = threadIdx.x;
    sXe[c] = emb_x[x[i] * EMB + c];
    __syncthreads();
    float a0 = 0.f, a1 = 0.f, a2 = 0.f, a3 = 0.f;
#pragma unroll 8
    for (int k = 0; k < EMB; k += 4) {
        a0 = fmaf(sXe[k + 0], w_ti[(k + 0) * EMB + c], a0);
        a1 = fmaf(sXe[k + 1], w_ti[(k + 1) * EMB + c], a1);
        a2 = fmaf(sXe[k + 2], w_ti[(k + 2) * EMB + c], a2);
        a3 = fmaf(sXe[k + 3], w_ti[(k + 3) * EMB + c], a3);
    }
    g_lin[i * EMB + c] = b_ti[c] + ((a0 + a1) + (a2 + a3));
}

// ---------------------------------------------------------------------------
// smem layout (float units)
#define SM_XV   0                        // 8448
#define SM_AGG  8448                     // u16 64*136 -> 4352 floats
#define SM_EA   12800                    // 4096
#define SM_LIN  16896                    // 1024
#define SM_XE   17920                    // 128
#define SM_TF   18048                    // 128 ints
#define SM_FLOATS 18176
#define SMEM_BYTES (SM_FLOATS * 4)       // 72704 B -> 3 CTAs/SM

__global__ __launch_bounds__(256, 3)
void conv_kernel(const int* __restrict__ x,
                 const int* __restrict__ edge_attr,
                 const int* __restrict__ tuplefeat,
                 const float* __restrict__ emb_x,
                 const float* __restrict__ emb_ea,
                 const float* __restrict__ emb_tf,
                 const float* __restrict__ b_conv,
                 const float* __restrict__ w_pred) {
    extern __shared__ float sm[];
    float* sXv   = sm + SM_XV;
    u16*   sAggB = (u16*)(sm + SM_AGG);
    float* sEa   = sm + SM_EA;
    float* sLin  = sm + SM_LIN;
    float* sXe   = sm + SM_XE;
    int*   sTf   = (int*)(sm + SM_TF);

    const int i    = blockIdx.x;
    const int tid  = threadIdx.x;
    const int base = (i >> 6) << 6;
    const int im   = i & 63;

    const int wid  = tid >> 5;
    const int lane = tid & 31;
    const int l4   = lane >> 2;
    const int lq   = lane & 3;

    // ldmatrix per-lane address
    const int rowsel = (lane & 7) + ((lane >> 3) & 1) * 8;
    const int colsel = (lane >> 4) * 8;
    const u32 aBase = (u32)__cvta_generic_to_shared(sAggB);
    const u32 aAddr = aBase + (rowsel * ASTB + colsel) * 2;

    if (tid < EMB) sXe[tid] = emb_x[x[i] * EMB + tid];
    if (tid < 128) sTf[tid] = tuplefeat[i * NT * 2 + tid];

    for (int idx = tid; idx < S * EMB; idx += 256) {
        const int j = idx >> 7, c = idx & 127;
        const int jn = ((im + j) & 63) + base;
        sLin[idx] = g_lin[jn * EMB + c];
    }
    for (int idx = tid; idx < 32 * EMB; idx += 256) {
        const int e = idx >> 7, c = idx & 127;
        const int ok = e >> 2, di = e & 3;
        const int kg = ((im + ok) & 63) + base;
        sEa[idx] = emb_ea[edge_attr[kg * 4 + di] * EMB + c];
    }
    __syncthreads();

    // Xv init (exact fp32)
    for (int idx = tid; idx < NT * EMB; idx += 256) {
        const int t = idx >> 7, c = idx & 127;
        const int j = t >> 3;
        const int tfi = sTf[t * 2 + (c >> 6)];
        const float tfv = emb_tf[tfi * (EMB / 2) + (c & 63)];
        sXv[t * XST + c] = sXe[c] * sLin[(j << 7) + c] * tfv;
    }
    __syncthreads();

    // message-stage constants: warp owns k = wid, lane owns 4 channels
    const int mk = wid;
    const int c4 = lane << 2;
    const float* eaK = sEa + ((mk << 2) << 7) + c4;

    for (int layer = 0; layer < NLAY; ++layer) {
        const float* __restrict__ B = b_conv + layer * EMB;
        const u32* wf = g_wfrag + (layer * 8 + wid) * 1024 + lane * 4;

        // --- prefetch first half of this layer's B-frags (hidden by msgs) ---
        uint4 bf[8];
        bf[0] = *(const uint4*)(wf + 0 * 128);
        bf[1] = *(const uint4*)(wf + 1 * 128);
        bf[2] = *(const uint4*)(wf + 2 * 128);
        bf[3] = *(const uint4*)(wf + 3 * 128);

        // --- messages + local segment_sum -> bf16 into sAggB ---
        {
            const float4 e0 = *(const float4*)(eaK + 0 * EMB);
            const float4 e1 = *(const float4*)(eaK + 1 * EMB);
            const float4 e2 = *(const float4*)(eaK + 2 * EMB);
            const float4 e3 = *(const float4*)(eaK + 3 * EMB);
            const u64 e0a = ((const u64*)&e0)[0], e0b = ((const u64*)&e0)[1];
            const u64 e1a = ((const u64*)&e1)[0], e1b = ((const u64*)&e1)[1];
            const u64 e2a = ((const u64*)&e2)[0], e2b = ((const u64*)&e2)[1];
            const u64 e3a = ((const u64*)&e3)[0], e3b = ((const u64*)&e3)[1];
#pragma unroll
            for (int j = 0; j < S; ++j) {
                const int t = (j << 3) + mk;
                u64 a = 0ull, b = 0ull;
                if (mk < 7) {
                    const u64* p = (const u64*)&sXv[(t + 1) * XST + c4];
                    FMA2(a, p[0], e0a, a); FMA2(b, p[1], e0b, b);
                }
                if (mk < 6) {
                    const u64* p = (const u64*)&sXv[(t + 2) * XST + c4];
                    FMA2(a, p[0], e1a, a); FMA2(b, p[1], e1b, b);
                }
                if (mk > 0) {
                    const u64* p = (const u64*)&sXv[(t - 1) * XST + c4];
                    FMA2(a, p[0], e2a, a); FMA2(b, p[1], e2b, b);
                }
                if (mk > 1) {
                    const u64* p = (const u64*)&sXv[(t - 2) * XST + c4];
                    FMA2(a, p[0], e3a, a); FMA2(b, p[1], e3b, b);
                }
                float f0, f1, f2, f3;
                UNPACK2(f0, f1, a); UNPACK2(f2, f3, b);
                u32 w0, w1;
                PACKBF(w0, f0, f1);
                PACKBF(w1, f2, f3);
                u64 pk = ((u64)w1 << 32) | w0;
                *(u64*)&sAggB[t * ASTB + c4] = pk;
            }
        }
        __syncthreads();

        // --- second half of B-frags; covered by first ks-steps ---
        bf[4] = *(const uint4*)(wf + 4 * 128);
        bf[5] = *(const uint4*)(wf + 5 * 128);
        bf[6] = *(const uint4*)(wf + 6 * 128);
        bf[7] = *(const uint4*)(wf + 7 * 128);

        // --- GEMM: warp = 64 rows x 16 cols ---
        float acc[4][2][4];
#pragma unroll
        for (int mt = 0; mt < 4; ++mt)
#pragma unroll
            for (int nt = 0; nt < 2; ++nt)
#pragma unroll
                for (int r = 0; r < 4; ++r) acc[mt][nt][r] = 0.f;

#pragma unroll
        for (int ks = 0; ks < 8; ++ks) {
            u32 afr[4][4];
#pragma unroll
            for (int mt = 0; mt < 4; ++mt)
                LDSM4(afr[mt], aAddr + (mt * 16 * ASTB + ks * 16) * 2);
#pragma unroll
            for (int mt = 0; mt < 4; ++mt) {
                MMA_BF16(acc[mt][0], afr[mt], bf[ks].x, bf[ks].y);
                MMA_BF16(acc[mt][1], afr[mt], bf[ks].z, bf[ks].w);
            }
        }

        // --- epilogue: bias + relu + residual (fp32 carry, float2 RMW) ---
        const int col0 = wid * 16 + 2 * lq;
        const float2 bb0 = *(const float2*)(B + col0);
        const float2 bb1 = *(const float2*)(B + col0 + 8);
#pragma unroll
        for (int mt = 0; mt < 4; ++mt) {
            const int row = mt * 16 + l4;
#pragma unroll
            for (int nt = 0; nt < 2; ++nt) {
                const int col = col0 + nt * 8;
                const float bx = nt ? bb1.x : bb0.x;
                const float by = nt ? bb1.y : bb0.y;
                float2* p0 = (float2*)&sXv[row * XST + col];
                float2* p1 = (float2*)&sXv[(row + 8) * XST + col];
                float v0 = acc[mt][nt][0] + bx; v0 = v0 > 0.f ? v0 : 0.f;
                float v1 = acc[mt][nt][1] + by; v1 = v1 > 0.f ? v1 : 0.f;
                float v2 = acc[mt][nt][2] + bx; v2 = v2 > 0.f ? v2 : 0.f;
                float v3 = acc[mt][nt][3] + by; v3 = v3 > 0.f ? v3 : 0.f;
                float2 a0 = *p0; a0.x += v0; a0.y += v1; *p0 = a0;
                float2 a1 = *p1; a1.x += v2; a1.y += v3; *p1 = a1;
            }
        }
        __syncthreads();
    }

    // --- pooling: max over k per pair ---
    for (int idx = tid; idx < S * EMB; idx += 256) {
        const int j = idx >> 7, c = idx & 127;
        const float* row = sXv + (j << 3) * XST + c;
        float m = row[0];
#pragma unroll
        for (int k = 1; k < S; ++k) m = fmaxf(m, row[k * XST]);
        sLin[idx] = m;
    }
    __syncthreads();

    // --- node dot w_pred ---
    float part = 0.f;
    for (int c = tid; c < EMB; c += 256) {
        float nv = 0.f;
#pragma unroll
        for (int j = 0; j < S; ++j) nv += sLin[(j << 7) + c];
        part += nv * w_pred[c];
    }
#pragma unroll
    for (int o = 16; o; o >>= 1) part += __shfl_down_sync(0xffffffffu, part, o);
    if ((tid & 31) == 0) sXe[tid >> 5] = part;
    __syncthreads();
    if (tid == 0) {
        float s = 0.f;
#pragma unroll
        for (int w = 0; w < 8; ++w) s += sXe[w];
        g_node_s[i] = s;
    }
}

// ---------------------------------------------------------------------------
__global__ void final_kernel(const float* __restrict__ b_pred,
                             float* __restrict__ out) {
    __shared__ float sp[2];
    const int g = blockIdx.x;
    const int t = threadIdx.x;       // 64
    float v = g_node_s[g * NPG + t];
#pragma unroll
    for (int o = 16; o; o >>= 1) v += __shfl_down_sync(0xffffffffu, v, o);
    if ((t & 31) == 0) sp[t >> 5] = v;
    __syncthreads();
    if (t == 0) out[g] = sp[0] + sp[1] + b_pred[0];
}

// ---------------------------------------------------------------------------
extern "C" void kernel_launch(void* const* d_in, const int* in_sizes, int n_in,
                              void* d_out, int out_size) {
    const int* x         = (const int*)d_in[0];
    const int* edge_attr = (const int*)d_in[1];
    const int* tuplefeat = (const int*)d_in[2];
    int w0 = (n_in >= 21 && in_sizes[11] == 1) ? 12 : 11;
    const float* emb_x  = (const float*)d_in[w0 + 0];
    const float* emb_ea = (const float*)d_in[w0 + 1];
    const float* emb_tf = (const float*)d_in[w0 + 2];
    const float* w_ti   = (const float*)d_in[w0 + 3];
    const float* b_ti   = (const float*)d_in[w0 + 4];
    const float* w_conv = (const float*)d_in[w0 + 5];
    const float* b_conv = (const float*)d_in[w0 + 6];
    const float* w_pred = (const float*)d_in[w0 + 7];
    const float* b_pred = (const float*)d_in[w0 + 8];
    float* out = (float*)d_out;

    cudaFuncSetAttribute(conv_kernel,
                         cudaFuncAttributeMaxDynamicSharedMemorySize, SMEM_BYTES);

    wfrag_kernel<<<NLAY * 8 * 8 * 32 * 4 / 256, 256>>>(w_conv);
    lin_kernel<<<NN, EMB>>>(x, emb_x, w_ti, b_ti);
    conv_kernel<<<NN, 256, SMEM_BYTES>>>(x, edge_attr, tuplefeat,
                                         emb_x, emb_ea, emb_tf,
                                         b_conv, w_pred);
    final_kernel<<<NPG, NPG>>>(b_pred, out);
}

// round 14
// speedup vs baseline: 6.2057x; 1.1668x over previous
#include <cuda_runtime.h>
#include <cuda_bf16.h>

// I2GNN fixed structure: G=64, N_PER_G=64, S=8, DEG=4, EMB=128, LAYERS=5.
// R10: residual Xv in registers (fp32), bf16x2 message math, bf16 Xv/Agg smem,
//      register pooling via shuffles. bf16 m16n8k16 MMA, fp32 accumulate.

#define NN   4096
#define NPG  64
#define EMB  128
#define S    8
#define NLAY 5
#define NT   64
#define XW   68          // XvB/AggB row stride in u32 words (136 u16)

__device__ float g_lin[NN * EMB];
__device__ float g_node_s[NN];
// bf16 B frags: [layer][warp(8)][ks(8)][lane(32)][4]
__device__ unsigned int g_wfrag[NLAY * 8 * 8 * 32 * 4];

typedef unsigned long long u64;
typedef unsigned int u32;
typedef unsigned short u16;

#define PACKBF(u, lo, hi) \
    asm("cvt.rn.bf16x2.f32 %0, %1, %2;" : "=r"(u) : "f"(hi), "f"(lo))
#define BFFMA2(d, a, b, c) \
    asm("fma.rn.bf16x2 %0, %1, %2, %3;" : "=r"(d) : "r"(a), "r"(b), "r"(c))

#define MMA_BF16(c, a, b0, b1) \
    asm("mma.sync.aligned.m16n8k16.row.col.f32.bf16.bf16.f32 " \
        "{%0,%1,%2,%3}, {%4,%5,%6,%7}, {%8,%9}, {%0,%1,%2,%3};" \
        : "+f"((c)[0]), "+f"((c)[1]), "+f"((c)[2]), "+f"((c)[3]) \
        : "r"((a)[0]), "r"((a)[1]), "r"((a)[2]), "r"((a)[3]), \
          "r"(b0), "r"(b1))

#define LDSM4(r, addr) \
    asm("ldmatrix.sync.aligned.m8n8.x4.shared.b16 {%0,%1,%2,%3}, [%4];" \
        : "=r"((r)[0]), "=r"((r)[1]), "=r"((r)[2]), "=r"((r)[3]) : "r"(addr))

// ---------------------------------------------------------------------------
__global__ void wfrag_kernel(const float* __restrict__ w_conv) {
    const int idx = blockIdx.x * 256 + threadIdx.x;     // 40960 total
    const int r     = idx & 3;
    const int lane  = (idx >> 2) & 31;
    const int ks    = (idx >> 7) & 7;
    const int w     = (idx >> 10) & 7;
    const int layer = idx >> 13;
    const int nt = r >> 1, reg = r & 1;
    const int col = w * 16 + nt * 8 + (lane >> 2);
    const int k0  = ks * 16 + reg * 8 + (lane & 3) * 2;
    const float lo = w_conv[layer * EMB * EMB + k0 * EMB + col];
    const float hi = w_conv[layer * EMB * EMB + (k0 + 1) * EMB + col];
    u32 u; PACKBF(u, lo, hi);
    g_wfrag[idx] = u;
}

// ---------------------------------------------------------------------------
__global__ void lin_kernel(const int* __restrict__ x,
                           const float* __restrict__ emb_x,
                           const float* __restrict__ w_ti,
                           const float* __restrict__ b_ti) {
    __shared__ float sXe[EMB];
    const int i = blockIdx.x;
    const int c = threadIdx.x;
    sXe[c] = emb_x[x[i] * EMB + c];
    __syncthreads();
    float a0 = 0.f, a1 = 0.f, a2 = 0.f, a3 = 0.f;
#pragma unroll 8
    for (int k = 0; k < EMB; k += 4) {
        a0 = fmaf(sXe[k + 0], w_ti[(k + 0) * EMB + c], a0);
        a1 = fmaf(sXe[k + 1], w_ti[(k + 1) * EMB + c], a1);
        a2 = fmaf(sXe[k + 2], w_ti[(k + 2) * EMB + c], a2);
        a3 = fmaf(sXe[k + 3], w_ti[(k + 3) * EMB + c], a3);
    }
    g_lin[i * EMB + c] = b_ti[c] + ((a0 + a1) + (a2 + a3));
}

// ---------------------------------------------------------------------------
// smem layout (bytes)
#define SMB_XVB 0          // u32[64*68]  17408
#define SMB_AGG 17408      // u32[64*68]  17408
#define SMB_EA  34816      // u32[32*64]   8192
#define SMB_LIN 43008      // f32[8*128]   4096
#define SMB_XE  47104      // f32[128]      512
#define SMB_TF  47616      // int[128]      512
#define SMB_RED 48128      // f32[8]         32
#define SMEM_BYTES 48160

__global__ __launch_bounds__(256, 3)
void conv_kernel(const int* __restrict__ x,
                 const int* __restrict__ edge_attr,
                 const int* __restrict__ tuplefeat,
                 const float* __restrict__ emb_x,
                 const float* __restrict__ emb_ea,
                 const float* __restrict__ emb_tf,
                 const float* __restrict__ b_conv,
                 const float* __restrict__ w_pred) {
    extern __shared__ char smraw[];
    u32*   sXvB = (u32*)(smraw + SMB_XVB);
    u32*   sAgg = (u32*)(smraw + SMB_AGG);
    u32*   sEaB = (u32*)(smraw + SMB_EA);
    float* sLin = (float*)(smraw + SMB_LIN);
    float* sXe  = (float*)(smraw + SMB_XE);
    int*   sTf  = (int*)(smraw + SMB_TF);
    float* sRed = (float*)(smraw + SMB_RED);

    const int i    = blockIdx.x;
    const int tid  = threadIdx.x;
    const int base = (i >> 6) << 6;
    const int im   = i & 63;

    const int wid  = tid >> 5;
    const int lane = tid & 31;
    const int l4   = lane >> 2;
    const int lq   = lane & 3;

    // ldmatrix per-lane address (A frags from sAgg)
    const int rowsel = (lane & 7) + ((lane >> 3) & 1) * 8;
    const int colsel = (lane >> 4) * 8;
    const u32 aBase = (u32)__cvta_generic_to_shared(sAgg);
    const u32 aAddr = aBase + (rowsel * (XW * 2) + colsel) * 2;

    // ---- stage embeddings ----
    if (tid < EMB) sXe[tid] = emb_x[x[i] * EMB + tid];
    if (tid < 128) sTf[tid] = tuplefeat[i * NT * 2 + tid];

    for (int idx = tid; idx < S * EMB; idx += 256) {
        const int j = idx >> 7, c = idx & 127;
        const int jn = ((im + j) & 63) + base;
        sLin[idx] = g_lin[jn * EMB + c];
    }
    // Ea -> bf16x2 smem: [e(32)][cw(64)]
    for (int idx = tid; idx < 32 * 64; idx += 256) {
        const int e = idx >> 6, cw = idx & 63;
        const int ok = e >> 2, di = e & 3;
        const int kg = ((im + ok) & 63) + base;
        const float* row = emb_ea + edge_attr[kg * 4 + di] * EMB + cw * 2;
        u32 u; PACKBF(u, row[0], row[1]);
        sEaB[idx] = u;
    }
    __syncthreads();

    // ---- XvB init (bf16 smem copy) ----
    for (int idx = tid; idx < NT * 64; idx += 256) {
        const int t = idx >> 6, cw = idx & 63;
        const int c0 = cw * 2;
        const int j = t >> 3;
        const int tfi = sTf[t * 2 + (cw >> 5)];
        const float2 tf2 = *(const float2*)(emb_tf + tfi * 64 + (c0 & 63));
        const float v0 = sXe[c0] * sLin[(j << 7) + c0] * tf2.x;
        const float v1 = sXe[c0 + 1] * sLin[(j << 7) + c0 + 1] * tf2.y;
        u32 u; PACKBF(u, v0, v1);
        sXvB[t * XW + cw] = u;
    }

    // ---- xv register fragment init (exact fp32) ----
    float xv[4][2][4];
#pragma unroll
    for (int mt = 0; mt < 4; ++mt)
#pragma unroll
        for (int nt = 0; nt < 2; ++nt)
#pragma unroll
            for (int r = 0; r < 4; ++r) {
                const int row = mt * 16 + ((r >> 1) & 1) * 8 + l4;
                const int col = wid * 16 + nt * 8 + 2 * lq + (r & 1);
                const int tfi = sTf[row * 2 + (col >> 6)];
                const float tfv = emb_tf[tfi * 64 + (col & 63)];
                xv[mt][nt][r] = sXe[col] * sLin[((row >> 3) << 7) + col] * tfv;
            }
    __syncthreads();

    const int mk = wid;                 // message k owned by this warp
    const u32* wfbase = g_wfrag + wid * 1024 + lane * 4;

    for (int layer = 0; layer < NLAY; ++layer) {
        const float* __restrict__ B = b_conv + layer * EMB;
        const u32* wf = wfbase + layer * 8192;

        // --- messages, all bf16x2 ---
        {
            const u32* ea = sEaB + (mk << 8) + lane * 2;   // 4 rows stride 64
            const u32 e0a = ea[0],       e0b = ea[1];
            const u32 e1a = ea[64],      e1b = ea[65];
            const u32 e2a = ea[128],     e2b = ea[129];
            const u32 e3a = ea[192],     e3b = ea[193];
#pragma unroll
            for (int j = 0; j < S; ++j) {
                const int t = (j << 3) + mk;
                u32 a = 0u, b = 0u;
                if (mk < 7) {
                    const u32* p = &sXvB[(t + 1) * XW + lane * 2];
                    BFFMA2(a, p[0], e0a, a); BFFMA2(b, p[1], e0b, b);
                }
                if (mk < 6) {
                    const u32* p = &sXvB[(t + 2) * XW + lane * 2];
                    BFFMA2(a, p[0], e1a, a); BFFMA2(b, p[1], e1b, b);
                }
                if (mk > 0) {
                    const u32* p = &sXvB[(t - 1) * XW + lane * 2];
                    BFFMA2(a, p[0], e2a, a); BFFMA2(b, p[1], e2b, b);
                }
                if (mk > 1) {
                    const u32* p = &sXvB[(t - 2) * XW + lane * 2];
                    BFFMA2(a, p[0], e3a, a); BFFMA2(b, p[1], e3b, b);
                }
                sAgg[t * XW + lane * 2]     = a;
                sAgg[t * XW + lane * 2 + 1] = b;
            }
        }
        __syncthreads();

        // --- GEMM: warp = 64 rows x 16 cols, rolling B prefetch ---
        float acc[4][2][4];
#pragma unroll
        for (int mt = 0; mt < 4; ++mt)
#pragma unroll
            for (int nt = 0; nt < 2; ++nt)
#pragma unroll
                for (int r = 0; r < 4; ++r) acc[mt][nt][r] = 0.f;

        uint4 bq[3];
        bq[0] = *(const uint4*)(wf);
        bq[1] = *(const uint4*)(wf + 128);
#pragma unroll
        for (int ks = 0; ks < 8; ++ks) {
            if (ks < 6) bq[(ks + 2) % 3] = *(const uint4*)(wf + (ks + 2) * 128);
            const uint4 bb = bq[ks % 3];
#pragma unroll
            for (int mt = 0; mt < 4; ++mt) {
                u32 afr[4];
                LDSM4(afr, aAddr + (mt * 16 * XW * 2 + ks * 16) * 2);
                MMA_BF16(acc[mt][0], afr, bb.x, bb.y);
                MMA_BF16(acc[mt][1], afr, bb.z, bb.w);
            }
        }

        // --- epilogue: xv += relu(acc + b); pack bf16 -> sXvB ---
        const int col0 = wid * 16 + 2 * lq;
        const float2 bb0 = *(const float2*)(B + col0);
        const float2 bb1 = *(const float2*)(B + col0 + 8);
#pragma unroll
        for (int mt = 0; mt < 4; ++mt) {
            const int row = mt * 16 + l4;
#pragma unroll
            for (int nt = 0; nt < 2; ++nt) {
                const float bx = nt ? bb1.x : bb0.x;
                const float by = nt ? bb1.y : bb0.y;
                float v0 = acc[mt][nt][0] + bx; v0 = v0 > 0.f ? v0 : 0.f;
                float v1 = acc[mt][nt][1] + by; v1 = v1 > 0.f ? v1 : 0.f;
                float v2 = acc[mt][nt][2] + bx; v2 = v2 > 0.f ? v2 : 0.f;
                float v3 = acc[mt][nt][3] + by; v3 = v3 > 0.f ? v3 : 0.f;
                xv[mt][nt][0] += v0;
                xv[mt][nt][1] += v1;
                xv[mt][nt][2] += v2;
                xv[mt][nt][3] += v3;
                u32 u0, u1;
                PACKBF(u0, xv[mt][nt][0], xv[mt][nt][1]);
                PACKBF(u1, xv[mt][nt][2], xv[mt][nt][3]);
                const int w0 = row * XW + wid * 8 + nt * 4 + lq;
                sXvB[w0] = u0;
                sXvB[w0 + 8 * XW] = u1;
            }
        }
        __syncthreads();
    }

    // --- pooling in registers: max over k (l4 lanes) then sum over j ---
    float node2[2][2] = {{0.f, 0.f}, {0.f, 0.f}};
#pragma unroll
    for (int mt = 0; mt < 4; ++mt)
#pragma unroll
        for (int nt = 0; nt < 2; ++nt)
#pragma unroll
            for (int r = 0; r < 4; ++r) {
                float v = xv[mt][nt][r];
                v = fmaxf(v, __shfl_xor_sync(0xffffffffu, v, 4));
                v = fmaxf(v, __shfl_xor_sync(0xffffffffu, v, 8));
                v = fmaxf(v, __shfl_xor_sync(0xffffffffu, v, 16));
                node2[nt][r & 1] += v;     // sums over mt and row-half (= j)
            }
    // dot with w_pred on this warp's 16 cols
    const int colb = wid * 16 + 2 * lq;
    float part = node2[0][0] * w_pred[colb]
               + node2[0][1] * w_pred[colb + 1]
               + node2[1][0] * w_pred[colb + 8]
               + node2[1][1] * w_pred[colb + 9];
    if (l4 != 0) part = 0.f;
#pragma unroll
    for (int o = 16; o; o >>= 1) part += __shfl_down_sync(0xffffffffu, part, o);
    if (lane == 0) sRed[wid] = part;
    __syncthreads();
    if (tid == 0) {
        float s = 0.f;
#pragma unroll
        for (int w = 0; w < 8; ++w) s += sRed[w];
        g_node_s[i] = s;
    }
}

// ---------------------------------------------------------------------------
__global__ void final_kernel(const float* __restrict__ b_pred,
                             float* __restrict__ out) {
    __shared__ float sp[2];
    const int g = blockIdx.x;
    const int t = threadIdx.x;       // 64
    float v = g_node_s[g * NPG + t];
#pragma unroll
    for (int o = 16; o; o >>= 1) v += __shfl_down_sync(0xffffffffu, v, o);
    if ((t & 31) == 0) sp[t >> 5] = v;
    __syncthreads();
    if (t == 0) out[g] = sp[0] + sp[1] + b_pred[0];
}

// ---------------------------------------------------------------------------
extern "C" void kernel_launch(void* const* d_in, const int* in_sizes, int n_in,
                              void* d_out, int out_size) {
    const int* x         = (const int*)d_in[0];
    const int* edge_attr = (const int*)d_in[1];
    const int* tuplefeat = (const int*)d_in[2];
    int w0 = (n_in >= 21 && in_sizes[11] == 1) ? 12 : 11;
    const float* emb_x  = (const float*)d_in[w0 + 0];
    const float* emb_ea = (const float*)d_in[w0 + 1];
    const float* emb_tf = (const float*)d_in[w0 + 2];
    const float* w_ti   = (const float*)d_in[w0 + 3];
    const float* b_ti   = (const float*)d_in[w0 + 4];
    const float* w_conv = (const float*)d_in[w0 + 5];
    const float* b_conv = (const float*)d_in[w0 + 6];
    const float* w_pred = (const float*)d_in[w0 + 7];
    const float* b_pred = (const float*)d_in[w0 + 8];
    float* out = (float*)d_out;

    cudaFuncSetAttribute(conv_kernel,
                         cudaFuncAttributeMaxDynamicSharedMemorySize, SMEM_BYTES);

    wfrag_kernel<<<NLAY * 8 * 8 * 32 * 4 / 256, 256>>>(w_conv);
    lin_kernel<<<NN, EMB>>>(x, emb_x, w_ti, b_ti);
    conv_kernel<<<NN, 256, SMEM_BYTES>>>(x, edge_attr, tuplefeat,
                                         emb_x, emb_ea, emb_tf,
                                         b_conv, w_pred);
    final_kernel<<<NPG, NPG>>>(b_pred, out);
}